// round 16
// baseline (speedup 1.0000x reference)
#include <cuda_runtime.h>
#include <cuda_fp16.h>
#include <math.h>
#include <stdint.h>

// Problem constants
constexpr int C_B    = 2;
constexpr int C_T    = 2048;
constexpr int C_HID  = 2048;
constexpr int C_H    = 16;
constexpr int C_D    = 128;
constexpr int C_WIN  = 512;
constexpr int C_QC   = 512;
constexpr int C_G    = 4;
constexpr int C_INTER= 2048;
constexpr int C_TOK  = C_B * C_T;
constexpr int TILE_H = 8192;            // halves per 16KB GEMM tile [128 x 64]

// ---------------------------------------------------------------------------
// Scratch
// ---------------------------------------------------------------------------
__device__ __align__(1024) __half g_h_t  [(size_t)32 * 32 * TILE_H];
__device__ __align__(1024) __half g_hc_t [(size_t)32 * 8  * TILE_H];
__device__ __align__(1024) __half g_att_t[(size_t)32 * 32 * TILE_H];
__device__ __align__(1024) __half g_y1_t [(size_t)32 * 128* TILE_H];
__device__ __align__(1024) __half g_wqc_t[(size_t)4  * 32 * TILE_H];
__device__ __align__(1024) __half g_wqu_t[(size_t)16 * 8  * TILE_H];
__device__ __align__(1024) __half g_wkv_t[(size_t)2  * 32 * TILE_H];
__device__ __align__(1024) __half g_w1_t [(size_t)4 * 16 * 8 * TILE_H];
__device__ __align__(1024) __half g_w2_t [(size_t)16 * 128* TILE_H];
__device__ float g_q [C_TOK * C_H * C_D];
__device__ float g_kv[C_TOK * 2 * C_D];
__device__ float g_rope[C_T * 64];      // [pos][lane*2] = cos, +1 = sin
// Attention tiles: [64 rows x 256B] fp16, chunk-swizzled (chunk ^ (row&7))
__device__ __align__(1024) __half g_qs[(size_t)C_B * C_H * 32 * 8192];  // scaled q
__device__ __align__(1024) __half g_ks[(size_t)C_B * 32 * 8192];
__device__ __align__(1024) __half g_vs[(size_t)C_B * 32 * 8192];

// ---------------------------------------------------------------------------
__device__ __forceinline__ uint32_t sw128(uint32_t off) {
    return off ^ ((off >> 3) & 0x70);
}

__device__ __forceinline__ void mma_f16(float& c0, float& c1, float& c2, float& c3,
                                        uint32_t a0, uint32_t a1, uint32_t a2, uint32_t a3,
                                        uint32_t b0, uint32_t b1) {
    asm volatile(
        "mma.sync.aligned.m16n8k16.row.col.f32.f16.f16.f32 "
        "{%0,%1,%2,%3}, {%4,%5,%6,%7}, {%8,%9}, {%0,%1,%2,%3};"
        : "+f"(c0), "+f"(c1), "+f"(c2), "+f"(c3)
        : "r"(a0), "r"(a1), "r"(a2), "r"(a3), "r"(b0), "r"(b1));
}

__device__ __forceinline__ void ldsm4(uint32_t& r0, uint32_t& r1, uint32_t& r2, uint32_t& r3,
                                      uint32_t addr) {
    asm volatile("ldmatrix.sync.aligned.m8n8.x4.shared.b16 {%0,%1,%2,%3}, [%4];"
                 : "=r"(r0), "=r"(r1), "=r"(r2), "=r"(r3) : "r"(addr));
}
__device__ __forceinline__ void ldsm4t(uint32_t& r0, uint32_t& r1, uint32_t& r2, uint32_t& r3,
                                       uint32_t addr) {
    asm volatile("ldmatrix.sync.aligned.m8n8.x4.trans.shared.b16 {%0,%1,%2,%3}, [%4];"
                 : "=r"(r0), "=r"(r1), "=r"(r2), "=r"(r3) : "r"(addr));
}

__device__ __forceinline__ void mbar_init(uint32_t a, uint32_t cnt) {
    asm volatile("mbarrier.init.shared.b64 [%0], %1;" :: "r"(a), "r"(cnt) : "memory");
}
__device__ __forceinline__ void mbar_expect(uint32_t a, uint32_t bytes) {
    asm volatile("mbarrier.arrive.expect_tx.shared.b64 _, [%0], %1;"
                 :: "r"(a), "r"(bytes) : "memory");
}
__device__ __forceinline__ void mbar_wait(uint32_t a, uint32_t parity) {
    uint32_t done;
    asm volatile(
        "{\n\t.reg .pred p;\n\t"
        "mbarrier.try_wait.parity.acquire.cta.shared::cta.b64 p, [%1], %2;\n\t"
        "selp.b32 %0, 1, 0, p;\n\t}"
        : "=r"(done) : "r"(a), "r"(parity) : "memory");
    if (!done) {
        asm volatile(
            "{\n\t.reg .pred P1;\n\t"
            "WAIT_LOOP_%=:\n\t"
            "mbarrier.try_wait.parity.acquire.cta.shared::cta.b64 P1, [%0], %1, 0x989680;\n\t"
            "@P1 bra.uni WAIT_DONE_%=;\n\t"
            "bra.uni WAIT_LOOP_%=;\n\t"
            "WAIT_DONE_%=:\n\t}"
            :: "r"(a), "r"(parity) : "memory");
    }
}
__device__ __forceinline__ void bulk_g2s(uint32_t dst, const void* src, uint32_t bytes,
                                         uint32_t mbar) {
    asm volatile(
        "cp.async.bulk.shared::cta.global.mbarrier::complete_tx::bytes [%0], [%1], %2, [%3];"
        :: "r"(dst), "l"(src), "r"(bytes), "r"(mbar) : "memory");
}

// ---------------------------------------------------------------------------
// TMA-fed fp16 GEMM. 256 threads, 8 warps (4m x 2n), warp tile 32x64, S=3,
// 2 CTAs/SM. EPI 0: fp32 C. EPI 1: half tiled C.
// EPI 3: merged hc+kv launch (XT must be 1).
// XT: x-tiles produced per CTA (continuous pipeline, acc dump at boundary).
// ---------------------------------------------------------------------------
template<int EPI, int XT>
__global__ void __launch_bounds__(256, 2)
gemm_tma(const __half* __restrict__ A, const __half* __restrict__ B,
         const __half* __restrict__ B2,
         float* __restrict__ Cf, __half* __restrict__ Ch,
         int KT, int ldaT, int ldbT, int azA, int azB, int ldcP, int azC) {
    constexpr int S = 3;
    constexpr int STAGEB = 2 * 16384;

    extern __shared__ __align__(16) char smc[];
    const uint32_t sbase = (uint32_t)__cvta_generic_to_shared(smc);
    const uint32_t mb0   = sbase;
    const uint32_t data0 = sbase + 1024;

    const int tid  = threadIdx.x;
    const int warp = tid >> 5;
    const int lane = tid & 31;
    const int wm   = (warp >> 1) * 32;
    const int wn   = (warp & 1) * 64;
    const int grp  = lane >> 2;
    const int tig  = lane & 3;

    const bool second = (EPI == 3) && (blockIdx.x >= 4);
    const int bx = second ? blockIdx.x - 4 : blockIdx.x;

    const __half* Abase = A + ((size_t)blockIdx.y * ldaT + (size_t)blockIdx.z * azA) * TILE_H;
    const __half* Bsel  = second ? B2 : B;
    const __half* Bbase = Bsel + ((size_t)(bx * XT) * ldbT + (size_t)blockIdx.z * azB) * TILE_H;

    const int KT2 = XT * KT;

    auto bAddr = [&](int j) -> const __half* {
        if (XT == 1) return Bbase + (size_t)j * TILE_H;
        return Bbase + ((size_t)(j / KT) * ldbT + (j % KT)) * TILE_H;
    };
    auto aAddr = [&](int j) -> const __half* {
        if (XT == 1) return Abase + (size_t)j * TILE_H;
        return Abase + (size_t)(j % KT) * TILE_H;
    };

    if (tid == 0) {
        for (int s = 0; s < S; s++) mbar_init(mb0 + 8 * s, 1);
    }
    __syncthreads();
    if (tid == 0) {
        for (int i = 0; i < S - 1 && i < KT2; i++) {
            uint32_t mb = mb0 + 8 * i;
            mbar_expect(mb, 32768);
            bulk_g2s(data0 + i * STAGEB,         aAddr(i), 16384, mb);
            bulk_g2s(data0 + i * STAGEB + 16384, bAddr(i), 16384, mb);
        }
    }

    float acc[2][8][4];
#pragma unroll
    for (int i = 0; i < 2; i++)
#pragma unroll
        for (int j = 0; j < 8; j++)
#pragma unroll
            for (int r = 0; r < 4; r++) acc[i][j][r] = 0.f;

    const int aRow = wm + (lane & 15);
    const uint32_t aOff = (uint32_t)((lane >> 4) * 16);
    const uint32_t aXor = (uint32_t)((aRow & 7) << 4);
    const uint32_t aB0  = (uint32_t)(aRow * 128);
    const int bRow = wn + ((lane >> 4) & 1) * 8 + (lane & 7);
    const uint32_t bOff = (uint32_t)(((lane >> 3) & 1) * 16);
    const uint32_t bXor = (uint32_t)((lane & 7) << 4);
    const uint32_t bB0  = (uint32_t)(bRow * 128);

    auto epilogue = [&](int xsub) {
#pragma unroll
        for (int mi = 0; mi < 2; mi++) {
#pragma unroll
            for (int ni = 0; ni < 8; ni++) {
#pragma unroll
                for (int half_ = 0; half_ < 2; half_++) {
                    float v0 = acc[mi][ni][half_ * 2], v1 = acc[mi][ni][half_ * 2 + 1];
                    int mrow = wm + mi * 16 + grp + half_ * 8;
                    int kcol = wn + ni * 8 + tig * 2;
                    bool halfOut = (EPI == 1) || (EPI == 3 && !second);
                    int bxo = bx * XT + xsub;
                    if (halfOut) {
                        int ktile = bxo * 2 + (kcol >> 6) + blockIdx.z * azC;
                        int ldcT = (EPI == 3) ? 8 : ldcP;
                        size_t tb = ((size_t)blockIdx.y * ldcT + ktile) * TILE_H;
                        uint32_t o = sw128((uint32_t)(mrow * 128 + (kcol & 63) * 2));
                        __half2 hv;
                        hv.x = __float2half_rn(v0);
                        hv.y = __float2half_rn(v1);
                        *(__half2*)((char*)Ch + tb * 2 + o) = hv;
                    } else {
                        int ldc = (EPI == 3) ? 256 : ldcP;
                        size_t off = (size_t)(blockIdx.y * 128 + mrow) * ldc
                                   + bxo * 128 + kcol;
                        *(float2*)(Cf + off) = make_float2(v0, v1);
                    }
                    acc[mi][ni][half_ * 2]     = 0.f;
                    acc[mi][ni][half_ * 2 + 1] = 0.f;
                }
            }
        }
    };

    for (int kt = 0; kt < KT2; kt++) {
        mbar_wait(mb0 + 8 * (kt % S), (uint32_t)((kt / S) & 1));
        if (tid == 0) {
            int j = kt + S - 1;
            if (j < KT2) {
                uint32_t mb = mb0 + 8 * (j % S);
                uint32_t st = data0 + (j % S) * STAGEB;
                mbar_expect(mb, 32768);
                bulk_g2s(st,         aAddr(j), 16384, mb);
                bulk_g2s(st + 16384, bAddr(j), 16384, mb);
            }
        }
        const uint32_t stb = data0 + (kt % S) * STAGEB;
        const uint32_t aT = stb + aB0;
        const uint32_t bT = stb + 16384 + bB0;
#pragma unroll
        for (int ks = 0; ks < 4; ks++) {
            const uint32_t ak = ((uint32_t)(ks * 32) + aOff) ^ aXor;
            const uint32_t bk = ((uint32_t)(ks * 32) + bOff) ^ bXor;
            uint32_t ah[2][4], bh[4][4];
            ldsm4(ah[0][0], ah[0][1], ah[0][2], ah[0][3], aT + ak);
            ldsm4(ah[1][0], ah[1][1], ah[1][2], ah[1][3], aT + 16 * 128 + ak);
#pragma unroll
            for (int p = 0; p < 4; p++)
                ldsm4(bh[p][0], bh[p][1], bh[p][2], bh[p][3], bT + p * (16 * 128) + bk);
#pragma unroll
            for (int mi = 0; mi < 2; mi++)
#pragma unroll
                for (int ni = 0; ni < 8; ni++) {
                    const int p = ni >> 1, q = (ni & 1) * 2;
                    mma_f16(acc[mi][ni][0], acc[mi][ni][1], acc[mi][ni][2], acc[mi][ni][3],
                            ah[mi][0], ah[mi][1], ah[mi][2], ah[mi][3],
                            bh[p][q], bh[p][q + 1]);
                }
        }
        __syncthreads();
        if (XT > 1) {
            if ((kt + 1) % KT == 0) epilogue(kt / KT);
        }
    }
    if (XT == 1) epilogue(0);
}

// ---------------------------------------------------------------------------
// Pack megakernel: tiled weights/h + rope cos/sin table.
// ---------------------------------------------------------------------------
constexpr int PB_H    = 4096;
constexpr int PB_WQC  = 1024;
constexpr int PB_WQU  = 1024;
constexpr int PB_WK   = 256;
constexpr int PB_WV   = 256;
constexpr int PB_W1   = 4096;
constexpr int PB_W2   = 16384;
constexpr int PB_ROPE = 256;
constexpr int PB_TOTAL = PB_H + PB_WQC + PB_WQU + PB_WK + PB_WV + PB_W1 + PB_W2 + PB_ROPE;

__device__ __forceinline__ void pk_transpose(const float* __restrict__ src,
                                             __half* __restrict__ dst,
                                             int K, int N, int tile, int KTt, int nBase) {
    __shared__ float t[32][33];
    int tx = threadIdx.x & 31, ty = threadIdx.x >> 5;
    int ntx = N / 32;
    int n0 = (tile % ntx) * 32, k0 = (tile / ntx) * 32;
#pragma unroll
    for (int i = ty; i < 32; i += 8)
        t[i][tx] = src[(size_t)(k0 + i) * N + n0 + tx];
    __syncthreads();
#pragma unroll
    for (int i = ty; i < 32; i += 8) {
        int n = nBase + n0 + i;
        int k = k0 + tx;
        size_t tb = ((size_t)(n >> 7) * KTt + (k >> 6)) * TILE_H;
        uint32_t o = sw128((uint32_t)((n & 127) * 128 + (k & 63) * 2));
        *(__half*)((char*)dst + tb * 2 + o) = __float2half_rn(t[tx][i]);
    }
}

__global__ void __launch_bounds__(256)
pack_kernel(const float* __restrict__ h_in, __half* __restrict__ h_t,
            const float* __restrict__ wqc, __half* __restrict__ wqc_t,
            const float* __restrict__ wqu, __half* __restrict__ wqu_t,
            const float* __restrict__ wk,  const float* __restrict__ wv,
            __half* __restrict__ wkv_t,
            const float* __restrict__ w1,  __half* __restrict__ w1_t,
            const float* __restrict__ w2,  __half* __restrict__ w2_t,
            float* __restrict__ rope_tab) {
    int b = blockIdx.x;
    if (b < PB_H) {
        // one row of h (2048 floats) -> 8 halves per thread, one uint4 store
        int m = b;
        size_t mtb = (size_t)(m >> 7) * 32;
        uint32_t rowo = (uint32_t)((m & 127) * 128);
        const float4* s4 = (const float4*)(h_in + (size_t)m * 2048);
        int k0 = threadIdx.x * 8;
        float4 va = s4[threadIdx.x * 2];
        float4 vb = s4[threadIdx.x * 2 + 1];
        __half2 h01 = __floats2half2_rn(va.x, va.y);
        __half2 h23 = __floats2half2_rn(va.z, va.w);
        __half2 h45 = __floats2half2_rn(vb.x, vb.y);
        __half2 h67 = __floats2half2_rn(vb.z, vb.w);
        uint4 pk;
        pk.x = *(uint32_t*)&h01; pk.y = *(uint32_t*)&h23;
        pk.z = *(uint32_t*)&h45; pk.w = *(uint32_t*)&h67;
        size_t tb = (mtb + (k0 >> 6)) * TILE_H;
        uint32_t o = sw128(rowo + (uint32_t)((k0 & 63) * 2));
        *(uint4*)((char*)h_t + tb * 2 + o) = pk;
        return;
    }
    b -= PB_H;
    if (b < PB_WQC) { pk_transpose(wqc, wqc_t, C_HID, C_QC, b, 32, 0); return; }
    b -= PB_WQC;
    if (b < PB_WQU) { pk_transpose(wqu, wqu_t, C_QC, C_H * C_D, b, 8, 0); return; }
    b -= PB_WQU;
    if (b < PB_WK)  { pk_transpose(wk, wkv_t, C_HID, C_D, b, 32, 0); return; }
    b -= PB_WK;
    if (b < PB_WV)  { pk_transpose(wv, wkv_t, C_HID, C_D, b, 32, 128); return; }
    b -= PB_WV;
    if (b < PB_W1) {
        int g = b / 1024, tile = b % 1024;
        pk_transpose(w1 + (size_t)g * 512 * 2048,
                     w1_t + (size_t)g * 128 * TILE_H,
                     512, 2048, tile, 8, 0);
        return;
    }
    b -= PB_W1;
    if (b < PB_W2) { pk_transpose(w2, w2_t, C_G * C_INTER, C_HID, b, 128, 0); return; }
    b -= PB_W2;
    {
        int idx  = b * 256 + threadIdx.x;
        int pos  = idx >> 5;
        int lane = idx & 31;
        double invd = exp(-log(10000.0) * (double)(2 * lane) / 64.0);
        double ang  = (double)pos * invd;
        rope_tab[pos * 64 + lane * 2]     = (float)cos(ang);
        rope_tab[pos * 64 + lane * 2 + 1] = (float)sin(ang);
    }
}

// ---------------------------------------------------------------------------
// RoPE + RMSNorm, emitting fp16 swizzled attention tiles directly.
// ---------------------------------------------------------------------------
__device__ __forceinline__ void st_att_half(__half* base, size_t tile, int row, int d, float v) {
    int idx = row * 128 + ((((d >> 3) ^ (row & 7)) << 3) | (d & 7));
    base[tile * 8192 + idx] = __float2half_rn(v);
}

__global__ void __launch_bounds__(256)
rope_kernel(const float* __restrict__ q, const float* __restrict__ kv,
            const float* __restrict__ qw, const float* __restrict__ kw,
            const float* __restrict__ rope_tab,
            __half* __restrict__ qs, __half* __restrict__ ks, __half* __restrict__ vs) {
    int gid  = blockIdx.x * blockDim.x + threadIdx.x;
    int wid  = gid >> 5;
    int lane = threadIdx.x & 31;

    const float scale = 0.08838834764831845f;
    bool isq = wid < C_TOK * C_H;
    const float* row;
    const float* w;
    int token, h = 0;
    if (isq) {
        token = wid >> 4; h = wid & 15;
        row = q + (size_t)wid * C_D;
        w = qw;
    } else {
        int wk2 = wid - C_TOK * C_H;
        if (wk2 >= C_TOK) return;
        token = wk2;
        row = kv + (size_t)token * (2 * C_D);
        w = kw;
    }
    int b = token >> 11;
    int t = token & (C_T - 1);

    float a  = row[lane];
    float b2 = row[lane + 32];
    float c  = row[lane + 64];
    float e  = row[lane + 96];

    float cs = rope_tab[t * 64 + lane * 2];
    float sn = rope_tab[t * 64 + lane * 2 + 1];

    float r1 = a * cs - b2 * sn;
    float r2 = a * sn + b2 * cs;

    float ss = r1 * r1 + r2 * r2 + c * c + e * e;
#pragma unroll
    for (int off = 16; off; off >>= 1) ss += __shfl_xor_sync(0xffffffffu, ss, off);
    float rms = rsqrtf(ss * (1.0f / 128.0f) + 1e-6f);

    float v0 = r1 * rms * w[lane];
    float v1 = r2 * rms * w[lane + 32];
    float v2 = c  * rms * w[lane + 64];
    float v3 = e  * rms * w[lane + 96];

    int rowi = t & 63;
    if (isq) {
        size_t tile = (size_t)((b * 16 + h) * 32 + (t >> 6));
        st_att_half(qs, tile, rowi, lane,      v0 * scale);
        st_att_half(qs, tile, rowi, lane + 32, v1 * scale);
        st_att_half(qs, tile, rowi, lane + 64, v2 * scale);
        st_att_half(qs, tile, rowi, lane + 96, v3 * scale);
    } else {
        size_t tile = (size_t)(b * 32 + (t >> 6));
        st_att_half(ks, tile, rowi, lane,      v0);
        st_att_half(ks, tile, rowi, lane + 32, v1);
        st_att_half(ks, tile, rowi, lane + 64, v2);
        st_att_half(ks, tile, rowi, lane + 96, v3);
        st_att_half(vs, tile, rowi, lane,      row[128 + lane]);
        st_att_half(vs, tile, rowi, lane + 32, row[160 + lane]);
        st_att_half(vs, tile, rowi, lane + 64, row[192 + lane]);
        st_att_half(vs, tile, rowi, lane + 96, row[224 + lane]);
    }
}

// ---------------------------------------------------------------------------
// fp16 MMA flash attention (unchanged).
// ---------------------------------------------------------------------------
__global__ void __launch_bounds__(128)
attn_kernel(const __half* __restrict__ qs, const __half* __restrict__ ks,
            const __half* __restrict__ vs, const float* __restrict__ sink,
            __half* __restrict__ att_t) {
    constexpr int TB = 16384;
    extern __shared__ __align__(16) char smc[];
    const uint32_t sbase = (uint32_t)__cvta_generic_to_shared(smc);
    const uint32_t mbq  = sbase;
    const uint32_t mbk0 = sbase + 16;
    const uint32_t Qb   = sbase + 1024;
    const uint32_t St   = Qb + TB;

    int qt = blockIdx.x, h = blockIdx.y, b = blockIdx.z;
    int tid = threadIdx.x, warp = tid >> 5, lane = tid & 31;
    int grp = lane >> 2, tig = lane & 3;
    int wr = warp * 16;

    if (tid == 0) { mbar_init(mbq, 1); mbar_init(mbk0, 1); mbar_init(mbk0 + 8, 1); }
    __syncthreads();

    int ktLo = qt > 8 ? qt - 8 : 0;
    int nT = qt - ktLo + 1;

    if (tid == 0) {
        mbar_expect(mbq, TB);
        bulk_g2s(Qb, qs + (size_t)((b * 16 + h) * 32 + qt) * 8192, TB, mbq);
        for (int i = 0; i < 2 && i < nT; i++) {
            uint32_t mb = mbk0 + 8 * i;
            mbar_expect(mb, 2 * TB);
            bulk_g2s(St + i * 2 * TB,      ks + (size_t)(b * 32 + ktLo + i) * 8192, TB, mb);
            bulk_g2s(St + i * 2 * TB + TB, vs + (size_t)(b * 32 + ktLo + i) * 8192, TB, mb);
        }
    }

    float o[16][4];
#pragma unroll
    for (int i = 0; i < 16; i++)
#pragma unroll
        for (int r = 0; r < 4; r++) o[i][r] = 0.f;
    float mA = -1e30f, mB = -1e30f, lA = 0.f, lB = 0.f;

    mbar_wait(mbq, 0);

    const uint32_t axr  = (uint32_t)(lane & 7);
    const uint32_t aBase = Qb + (uint32_t)(wr + (lane & 15)) * 256;
    const uint32_t aSel = (uint32_t)(lane >> 4);
    const int bsrow_off = ((lane >> 4) & 1) * 8 + (lane & 7);
    const uint32_t bsel = (uint32_t)((lane >> 3) & 1);
    const int vrow_off  = ((lane >> 3) & 1) * 8 + (lane & 7);
    const uint32_t vsel = (uint32_t)((lane >> 4) & 1);

    for (int i = 0; i < nT; i++) {
        int kt = ktLo + i;
        mbar_wait(mbk0 + 8 * (i & 1), (uint32_t)((i >> 1) & 1));
        const uint32_t Kb = St + (uint32_t)((i & 1) * 2 * TB);
        const uint32_t Vb = Kb + TB;

        float sc[8][4];
#pragma unroll
        for (int ni = 0; ni < 8; ni++)
#pragma unroll
            for (int r = 0; r < 4; r++) sc[ni][r] = 0.f;

#pragma unroll
        for (int k8 = 0; k8 < 8; k8++) {
            uint32_t a0, a1, a2, a3;
            ldsm4(a0, a1, a2, a3, aBase + (((uint32_t)(2 * k8) + aSel) ^ axr) * 16);
#pragma unroll
            for (int np = 0; np < 4; np++) {
                uint32_t b0, b1, b2, b3;
                uint32_t srow = (uint32_t)(np * 16 + bsrow_off);
                ldsm4(b0, b1, b2, b3,
                      Kb + srow * 256 + (((uint32_t)(2 * k8) + bsel) ^ axr) * 16);
                mma_f16(sc[np*2][0], sc[np*2][1], sc[np*2][2], sc[np*2][3],
                        a0, a1, a2, a3, b0, b1);
                mma_f16(sc[np*2+1][0], sc[np*2+1][1], sc[np*2+1][2], sc[np*2+1][3],
                        a0, a1, a2, a3, b2, b3);
            }
        }

        if (kt == qt || kt + 8 == qt) {
            int tA2 = qt * 64 + wr + grp;
            int s00 = kt * 64 + tig * 2;
#pragma unroll
            for (int ni = 0; ni < 8; ni++) {
#pragma unroll
                for (int r = 0; r < 4; r++) {
                    int s = s00 + ni * 8 + (r & 1);
                    int t = tA2 + (r >> 1) * 8;
                    if (s > t || s < t - (C_WIN - 1)) sc[ni][r] = -1e30f;
                }
            }
        }

        float mxA = -1e30f, mxB = -1e30f;
#pragma unroll
        for (int ni = 0; ni < 8; ni++) {
            mxA = fmaxf(mxA, fmaxf(sc[ni][0], sc[ni][1]));
            mxB = fmaxf(mxB, fmaxf(sc[ni][2], sc[ni][3]));
        }
        mxA = fmaxf(mxA, __shfl_xor_sync(0xffffffffu, mxA, 1));
        mxA = fmaxf(mxA, __shfl_xor_sync(0xffffffffu, mxA, 2));
        mxB = fmaxf(mxB, __shfl_xor_sync(0xffffffffu, mxB, 1));
        mxB = fmaxf(mxB, __shfl_xor_sync(0xffffffffu, mxB, 2));
        float nmA = fmaxf(mA, mxA), nmB = fmaxf(mB, mxB);
        float cA = __expf(mA - nmA), cB = __expf(mB - nmB);
        mA = nmA; mB = nmB;
        float sA = 0.f, sB = 0.f;
#pragma unroll
        for (int ni = 0; ni < 8; ni++) {
            sc[ni][0] = __expf(sc[ni][0] - nmA);
            sc[ni][1] = __expf(sc[ni][1] - nmA);
            sc[ni][2] = __expf(sc[ni][2] - nmB);
            sc[ni][3] = __expf(sc[ni][3] - nmB);
            sA += sc[ni][0] + sc[ni][1];
            sB += sc[ni][2] + sc[ni][3];
        }
        sA += __shfl_xor_sync(0xffffffffu, sA, 1);
        sA += __shfl_xor_sync(0xffffffffu, sA, 2);
        sB += __shfl_xor_sync(0xffffffffu, sB, 1);
        sB += __shfl_xor_sync(0xffffffffu, sB, 2);
        lA = lA * cA + sA;
        lB = lB * cB + sB;
#pragma unroll
        for (int nd = 0; nd < 16; nd++) {
            o[nd][0] *= cA; o[nd][1] *= cA;
            o[nd][2] *= cB; o[nd][3] *= cB;
        }

#pragma unroll
        for (int kp = 0; kp < 4; kp++) {
            __half2 p0 = __floats2half2_rn(sc[2*kp][0],   sc[2*kp][1]);
            __half2 p1 = __floats2half2_rn(sc[2*kp][2],   sc[2*kp][3]);
            __half2 p2 = __floats2half2_rn(sc[2*kp+1][0], sc[2*kp+1][1]);
            __half2 p3 = __floats2half2_rn(sc[2*kp+1][2], sc[2*kp+1][3]);
            uint32_t pa0 = *(uint32_t*)&p0, pa1 = *(uint32_t*)&p1;
            uint32_t pa2 = *(uint32_t*)&p2, pa3 = *(uint32_t*)&p3;
            uint32_t vrow = (uint32_t)(kp * 16 + vrow_off);
#pragma unroll
            for (int dp = 0; dp < 8; dp++) {
                uint32_t b0, b1, b2, b3;
                ldsm4t(b0, b1, b2, b3,
                       Vb + vrow * 256 + (((uint32_t)(2 * dp) + vsel) ^ axr) * 16);
                mma_f16(o[dp*2][0], o[dp*2][1], o[dp*2][2], o[dp*2][3],
                        pa0, pa1, pa2, pa3, b0, b1);
                mma_f16(o[dp*2+1][0], o[dp*2+1][1], o[dp*2+1][2], o[dp*2+1][3],
                        pa0, pa1, pa2, pa3, b2, b3);
            }
        }

        __syncthreads();
        if (tid == 0 && i + 2 < nT) {
            uint32_t mb = mbk0 + 8 * (i & 1);
            mbar_expect(mb, 2 * TB);
            bulk_g2s(St + (i & 1) * 2 * TB,      ks + (size_t)(b * 32 + kt + 2) * 8192, TB, mb);
            bulk_g2s(St + (i & 1) * 2 * TB + TB, vs + (size_t)(b * 32 + kt + 2) * 8192, TB, mb);
        }
    }

    float sl = sink[h];
    float nmA = fmaxf(mA, sl);
    float fA  = __expf(mA - nmA);
    float dA  = lA * fA + __expf(sl - nmA);
    float scAf = fA / dA;
    float nmB = fmaxf(mB, sl);
    float fB  = __expf(mB - nmB);
    float dB  = lB * fB + __expf(sl - nmB);
    float scBf = fB / dB;

    int tokenA = b * C_T + qt * 64 + wr + grp;
    int tokenB = tokenA + 8;
#pragma unroll
    for (int nd = 0; nd < 16; nd++) {
        int col = h * 128 + nd * 8 + tig * 2;
        {
            size_t tb = ((size_t)(tokenA >> 7) * 32 + (col >> 6)) * TILE_H;
            uint32_t off = sw128((uint32_t)((tokenA & 127) * 128 + (col & 63) * 2));
            __half2 hv = __floats2half2_rn(o[nd][0] * scAf, o[nd][1] * scAf);
            *(__half2*)((char*)att_t + tb * 2 + off) = hv;
        }
        {
            size_t tb = ((size_t)(tokenB >> 7) * 32 + (col >> 6)) * TILE_H;
            uint32_t off = sw128((uint32_t)((tokenB & 127) * 128 + (col & 63) * 2));
            __half2 hv = __floats2half2_rn(o[nd][2] * scBf, o[nd][3] * scBf);
            *(__half2*)((char*)att_t + tb * 2 + off) = hv;
        }
    }
}

// ---------------------------------------------------------------------------
extern "C" void kernel_launch(void* const* d_in, const int* in_sizes, int n_in,
                              void* d_out, int out_size) {
    const float* h_in     = (const float*)d_in[0];
    const float* wq_comp  = (const float*)d_in[1];
    const float* wq_up    = (const float*)d_in[2];
    const float* wk       = (const float*)d_in[3];
    const float* wv       = (const float*)d_in[4];
    const float* q_norm_w = (const float*)d_in[5];
    const float* k_norm_w = (const float*)d_in[6];
    const float* sink     = (const float*)d_in[7];
    const float* out_w1   = (const float*)d_in[8];
    const float* out_w2   = (const float*)d_in[9];
    float* out = (float*)d_out;

    __half *h_t, *hc_t, *att_t, *y1_t, *wqc_t, *wqu_t, *wkv_t, *w1_t, *w2_t, *qsp, *ksp, *vsp;
    float *q, *kv, *rope_tab;
    cudaGetSymbolAddress((void**)&h_t,   g_h_t);
    cudaGetSymbolAddress((void**)&hc_t,  g_hc_t);
    cudaGetSymbolAddress((void**)&att_t, g_att_t);
    cudaGetSymbolAddress((void**)&y1_t,  g_y1_t);
    cudaGetSymbolAddress((void**)&wqc_t, g_wqc_t);
    cudaGetSymbolAddress((void**)&wqu_t, g_wqu_t);
    cudaGetSymbolAddress((void**)&wkv_t, g_wkv_t);
    cudaGetSymbolAddress((void**)&w1_t,  g_w1_t);
    cudaGetSymbolAddress((void**)&w2_t,  g_w2_t);
    cudaGetSymbolAddress((void**)&q,     g_q);
    cudaGetSymbolAddress((void**)&kv,    g_kv);
    cudaGetSymbolAddress((void**)&rope_tab, g_rope);
    cudaGetSymbolAddress((void**)&qsp,   g_qs);
    cudaGetSymbolAddress((void**)&ksp,   g_ks);
    cudaGetSymbolAddress((void**)&vsp,   g_vs);

    constexpr int SM_TMA  = 1024 + 3 * 32768;            // 99328 B (2 CTAs/SM)
    constexpr int SM_ATTN = 1024 + 16384 + 2 * 32768;    // 82944 B
    cudaFuncSetAttribute((const void*)gemm_tma<0,1>, cudaFuncAttributeMaxDynamicSharedMemorySize, SM_TMA);
    cudaFuncSetAttribute((const void*)gemm_tma<0,2>, cudaFuncAttributeMaxDynamicSharedMemorySize, SM_TMA);
    cudaFuncSetAttribute((const void*)gemm_tma<1,2>, cudaFuncAttributeMaxDynamicSharedMemorySize, SM_TMA);
    cudaFuncSetAttribute((const void*)gemm_tma<3,1>, cudaFuncAttributeMaxDynamicSharedMemorySize, SM_TMA);
    cudaFuncSetAttribute((const void*)attn_kernel, cudaFuncAttributeMaxDynamicSharedMemorySize, SM_ATTN);

    // [0] pack (+ rope table)
    pack_kernel<<<PB_TOTAL, 256>>>(h_in, h_t, wq_comp, wqc_t, wq_up, wqu_t,
                                   wk, wv, wkv_t, out_w1, w1_t, out_w2, w2_t, rope_tab);

    // [1] merged: hc = h @ wq_comp (x<4, half tiled) | kv = h @ wkv (x>=4, fp32)
    gemm_tma<3,1><<<dim3(6, 32), 256, SM_TMA>>>(
        h_t, wqc_t, wkv_t, kv, hc_t, 32, 32, 32, 0, 0, 0, 0);

    // [2] q = hc @ wq_up    -> fp32 (KT=8, XT=2 -> 16 iters/CTA)
    gemm_tma<0,2><<<dim3(8, 32), 256, SM_TMA>>>(
        hc_t, wqu_t, nullptr, q, nullptr, 8, 8, 8, 0, 0, C_H * C_D, 0);

    // [3] RoPE + RMSNorm -> fp16 swizzled q/k/v tiles
    {
        int warps = C_TOK * C_H + C_TOK;
        rope_kernel<<<(warps * 32 + 255) / 256, 256>>>(q, kv, q_norm_w, k_norm_w,
                                                       rope_tab, qsp, ksp, vsp);
    }

    // [4] flash attention -> att half tiled
    attn_kernel<<<dim3(32, 16, 2), 128, SM_ATTN>>>(qsp, ksp, vsp, sink, att_t);

    // [5] y1 = grouped att @ w1 -> half tiled (KT=8, XT=2 -> 16 iters/CTA)
    gemm_tma<1,2><<<dim3(8, 32, C_G), 256, SM_TMA>>>(
        att_t, w1_t, nullptr, nullptr, y1_t, 8, 32, 8, 8, 128, 128, 32);

    // [6] out = y1 @ out_w2 -> fp32 (KT=128)
    gemm_tma<0,1><<<dim3(16, 32), 256, SM_TMA>>>(
        y1_t, w2_t, nullptr, out, nullptr, 128, 128, 128, 0, 0, C_HID, 0);
}

// round 17
// speedup vs baseline: 1.0043x; 1.0043x over previous
#include <cuda_runtime.h>
#include <cuda_fp16.h>
#include <math.h>
#include <stdint.h>

// Problem constants
constexpr int C_B    = 2;
constexpr int C_T    = 2048;
constexpr int C_HID  = 2048;
constexpr int C_H    = 16;
constexpr int C_D    = 128;
constexpr int C_WIN  = 512;
constexpr int C_QC   = 512;
constexpr int C_G    = 4;
constexpr int C_INTER= 2048;
constexpr int C_TOK  = C_B * C_T;
constexpr int TILE_H = 8192;            // halves per 16KB GEMM tile [128 x 64]

// ---------------------------------------------------------------------------
// Scratch
// ---------------------------------------------------------------------------
__device__ __align__(1024) __half g_h_t  [(size_t)32 * 32 * TILE_H];
__device__ __align__(1024) __half g_hc_t [(size_t)32 * 8  * TILE_H];
__device__ __align__(1024) __half g_att_t[(size_t)32 * 32 * TILE_H];
__device__ __align__(1024) __half g_y1_t [(size_t)32 * 128* TILE_H];
__device__ __align__(1024) __half g_wqc_t[(size_t)4  * 32 * TILE_H];
__device__ __align__(1024) __half g_wqu_t[(size_t)16 * 8  * TILE_H];
__device__ __align__(1024) __half g_wkv_t[(size_t)2  * 32 * TILE_H];
__device__ __align__(1024) __half g_w1_t [(size_t)4 * 16 * 8 * TILE_H];
__device__ __align__(1024) __half g_w2_t [(size_t)16 * 128* TILE_H];
__device__ float g_q [C_TOK * C_H * C_D];
__device__ float g_kv[C_TOK * 2 * C_D];
__device__ float g_rope[C_T * 64];      // [pos][lane*2] = cos, +1 = sin
// Attention tiles: [64 rows x 256B] fp16, chunk-swizzled (chunk ^ (row&7))
__device__ __align__(1024) __half g_qs[(size_t)C_B * C_H * 32 * 8192];  // scaled q
__device__ __align__(1024) __half g_ks[(size_t)C_B * 32 * 8192];
__device__ __align__(1024) __half g_vs[(size_t)C_B * 32 * 8192];

// ---------------------------------------------------------------------------
__device__ __forceinline__ uint32_t sw128(uint32_t off) {
    return off ^ ((off >> 3) & 0x70);
}

__device__ __forceinline__ void mma_f16(float& c0, float& c1, float& c2, float& c3,
                                        uint32_t a0, uint32_t a1, uint32_t a2, uint32_t a3,
                                        uint32_t b0, uint32_t b1) {
    asm volatile(
        "mma.sync.aligned.m16n8k16.row.col.f32.f16.f16.f32 "
        "{%0,%1,%2,%3}, {%4,%5,%6,%7}, {%8,%9}, {%0,%1,%2,%3};"
        : "+f"(c0), "+f"(c1), "+f"(c2), "+f"(c3)
        : "r"(a0), "r"(a1), "r"(a2), "r"(a3), "r"(b0), "r"(b1));
}

__device__ __forceinline__ void ldsm4(uint32_t& r0, uint32_t& r1, uint32_t& r2, uint32_t& r3,
                                      uint32_t addr) {
    asm volatile("ldmatrix.sync.aligned.m8n8.x4.shared.b16 {%0,%1,%2,%3}, [%4];"
                 : "=r"(r0), "=r"(r1), "=r"(r2), "=r"(r3) : "r"(addr));
}
__device__ __forceinline__ void ldsm4t(uint32_t& r0, uint32_t& r1, uint32_t& r2, uint32_t& r3,
                                       uint32_t addr) {
    asm volatile("ldmatrix.sync.aligned.m8n8.x4.trans.shared.b16 {%0,%1,%2,%3}, [%4];"
                 : "=r"(r0), "=r"(r1), "=r"(r2), "=r"(r3) : "r"(addr));
}

__device__ __forceinline__ void mbar_init(uint32_t a, uint32_t cnt) {
    asm volatile("mbarrier.init.shared.b64 [%0], %1;" :: "r"(a), "r"(cnt) : "memory");
}
__device__ __forceinline__ void mbar_expect(uint32_t a, uint32_t bytes) {
    asm volatile("mbarrier.arrive.expect_tx.shared.b64 _, [%0], %1;"
                 :: "r"(a), "r"(bytes) : "memory");
}
__device__ __forceinline__ void mbar_arrive(uint32_t a) {
    asm volatile("mbarrier.arrive.release.cta.shared::cta.b64 _, [%0];"
                 :: "r"(a) : "memory");
}
__device__ __forceinline__ void mbar_wait(uint32_t a, uint32_t parity) {
    uint32_t done;
    asm volatile(
        "{\n\t.reg .pred p;\n\t"
        "mbarrier.try_wait.parity.acquire.cta.shared::cta.b64 p, [%1], %2;\n\t"
        "selp.b32 %0, 1, 0, p;\n\t}"
        : "=r"(done) : "r"(a), "r"(parity) : "memory");
    if (!done) {
        asm volatile(
            "{\n\t.reg .pred P1;\n\t"
            "WAIT_LOOP_%=:\n\t"
            "mbarrier.try_wait.parity.acquire.cta.shared::cta.b64 P1, [%0], %1, 0x989680;\n\t"
            "@P1 bra.uni WAIT_DONE_%=;\n\t"
            "bra.uni WAIT_LOOP_%=;\n\t"
            "WAIT_DONE_%=:\n\t}"
            :: "r"(a), "r"(parity) : "memory");
    }
}
__device__ __forceinline__ void bulk_g2s(uint32_t dst, const void* src, uint32_t bytes,
                                         uint32_t mbar) {
    asm volatile(
        "cp.async.bulk.shared::cta.global.mbarrier::complete_tx::bytes [%0], [%1], %2, [%3];"
        :: "r"(dst), "l"(src), "r"(bytes), "r"(mbar) : "memory");
}

// ---------------------------------------------------------------------------
// TMA-fed fp16 GEMM. 256 threads, 8 warps (4m x 2n), warp tile 32x64, S=3,
// 2 CTAs/SM. Producer/consumer mbarriers (full cnt=1 tx; empty cnt=8), no
// per-iter __syncthreads -> warps may skew up to S-1 chunks.
// EPI 0: fp32 C. EPI 1: half tiled C. EPI 3: merged hc+kv (XT must be 1).
// XT: x-tiles per CTA (continuous pipeline, acc dump at KT boundary).
// ---------------------------------------------------------------------------
template<int EPI, int XT>
__global__ void __launch_bounds__(256, 2)
gemm_tma(const __half* __restrict__ A, const __half* __restrict__ B,
         const __half* __restrict__ B2,
         float* __restrict__ Cf, __half* __restrict__ Ch,
         int KT, int ldaT, int ldbT, int azA, int azB, int ldcP, int azC) {
    constexpr int S = 3;
    constexpr int STAGEB = 2 * 16384;

    extern __shared__ __align__(16) char smc[];
    const uint32_t sbase = (uint32_t)__cvta_generic_to_shared(smc);
    const uint32_t mbF   = sbase;               // S full barriers
    const uint32_t mbE   = sbase + 8 * S;       // S empty barriers
    const uint32_t data0 = sbase + 1024;

    const int tid  = threadIdx.x;
    const int warp = tid >> 5;
    const int lane = tid & 31;
    const int wm   = (warp >> 1) * 32;
    const int wn   = (warp & 1) * 64;
    const int grp  = lane >> 2;
    const int tig  = lane & 3;

    const bool second = (EPI == 3) && (blockIdx.x >= 4);
    const int bx = second ? blockIdx.x - 4 : blockIdx.x;

    const __half* Abase = A + ((size_t)blockIdx.y * ldaT + (size_t)blockIdx.z * azA) * TILE_H;
    const __half* Bsel  = second ? B2 : B;
    const __half* Bbase = Bsel + ((size_t)(bx * XT) * ldbT + (size_t)blockIdx.z * azB) * TILE_H;

    const int KT2 = XT * KT;

    auto bAddr = [&](int j) -> const __half* {
        if (XT == 1) return Bbase + (size_t)j * TILE_H;
        return Bbase + ((size_t)(j / KT) * ldbT + (j % KT)) * TILE_H;
    };
    auto aAddr = [&](int j) -> const __half* {
        if (XT == 1) return Abase + (size_t)j * TILE_H;
        return Abase + (size_t)(j % KT) * TILE_H;
    };

    if (tid == 0) {
        for (int s = 0; s < S; s++) {
            mbar_init(mbF + 8 * s, 1);
            mbar_init(mbE + 8 * s, 8);
        }
    }
    __syncthreads();
    if (tid == 0) {
        for (int i = 0; i < S - 1 && i < KT2; i++) {
            uint32_t mb = mbF + 8 * i;
            mbar_expect(mb, 32768);
            bulk_g2s(data0 + i * STAGEB,         aAddr(i), 16384, mb);
            bulk_g2s(data0 + i * STAGEB + 16384, bAddr(i), 16384, mb);
        }
    }

    float acc[2][8][4];
#pragma unroll
    for (int i = 0; i < 2; i++)
#pragma unroll
        for (int j = 0; j < 8; j++)
#pragma unroll
            for (int r = 0; r < 4; r++) acc[i][j][r] = 0.f;

    const int aRow = wm + (lane & 15);
    const uint32_t aOff = (uint32_t)((lane >> 4) * 16);
    const uint32_t aXor = (uint32_t)((aRow & 7) << 4);
    const uint32_t aB0  = (uint32_t)(aRow * 128);
    const int bRow = wn + ((lane >> 4) & 1) * 8 + (lane & 7);
    const uint32_t bOff = (uint32_t)(((lane >> 3) & 1) * 16);
    const uint32_t bXor = (uint32_t)((lane & 7) << 4);
    const uint32_t bB0  = (uint32_t)(bRow * 128);

    auto epilogue = [&](int xsub) {
#pragma unroll
        for (int mi = 0; mi < 2; mi++) {
#pragma unroll
            for (int ni = 0; ni < 8; ni++) {
#pragma unroll
                for (int half_ = 0; half_ < 2; half_++) {
                    float v0 = acc[mi][ni][half_ * 2], v1 = acc[mi][ni][half_ * 2 + 1];
                    int mrow = wm + mi * 16 + grp + half_ * 8;
                    int kcol = wn + ni * 8 + tig * 2;
                    bool halfOut = (EPI == 1) || (EPI == 3 && !second);
                    int bxo = bx * XT + xsub;
                    if (halfOut) {
                        int ktile = bxo * 2 + (kcol >> 6) + blockIdx.z * azC;
                        int ldcT = (EPI == 3) ? 8 : ldcP;
                        size_t tb = ((size_t)blockIdx.y * ldcT + ktile) * TILE_H;
                        uint32_t o = sw128((uint32_t)(mrow * 128 + (kcol & 63) * 2));
                        __half2 hv;
                        hv.x = __float2half_rn(v0);
                        hv.y = __float2half_rn(v1);
                        *(__half2*)((char*)Ch + tb * 2 + o) = hv;
                    } else {
                        int ldc = (EPI == 3) ? 256 : ldcP;
                        size_t off = (size_t)(blockIdx.y * 128 + mrow) * ldc
                                   + bxo * 128 + kcol;
                        *(float2*)(Cf + off) = make_float2(v0, v1);
                    }
                    acc[mi][ni][half_ * 2]     = 0.f;
                    acc[mi][ni][half_ * 2 + 1] = 0.f;
                }
            }
        }
    };

    for (int kt = 0; kt < KT2; kt++) {
        mbar_wait(mbF + 8 * (kt % S), (uint32_t)((kt / S) & 1));
        if (tid == 0) {
            int j = kt + S - 1;
            if (j < KT2) {
                // reuse stage j%S: must wait for consumption of chunk j-S
                if (j >= S)
                    mbar_wait(mbE + 8 * (j % S), (uint32_t)(((j / S) - 1) & 1));
                uint32_t mb = mbF + 8 * (j % S);
                uint32_t st = data0 + (j % S) * STAGEB;
                mbar_expect(mb, 32768);
                bulk_g2s(st,         aAddr(j), 16384, mb);
                bulk_g2s(st + 16384, bAddr(j), 16384, mb);
            }
        }
        const uint32_t stb = data0 + (kt % S) * STAGEB;
        const uint32_t aT = stb + aB0;
        const uint32_t bT = stb + 16384 + bB0;
#pragma unroll
        for (int ks = 0; ks < 4; ks++) {
            const uint32_t ak = ((uint32_t)(ks * 32) + aOff) ^ aXor;
            const uint32_t bk = ((uint32_t)(ks * 32) + bOff) ^ bXor;
            uint32_t ah[2][4], bh[4][4];
            ldsm4(ah[0][0], ah[0][1], ah[0][2], ah[0][3], aT + ak);
            ldsm4(ah[1][0], ah[1][1], ah[1][2], ah[1][3], aT + 16 * 128 + ak);
#pragma unroll
            for (int p = 0; p < 4; p++)
                ldsm4(bh[p][0], bh[p][1], bh[p][2], bh[p][3], bT + p * (16 * 128) + bk);
#pragma unroll
            for (int mi = 0; mi < 2; mi++)
#pragma unroll
                for (int ni = 0; ni < 8; ni++) {
                    const int p = ni >> 1, q = (ni & 1) * 2;
                    mma_f16(acc[mi][ni][0], acc[mi][ni][1], acc[mi][ni][2], acc[mi][ni][3],
                            ah[mi][0], ah[mi][1], ah[mi][2], ah[mi][3],
                            bh[p][q], bh[p][q + 1]);
                }
        }
        if (lane == 0) mbar_arrive(mbE + 8 * (kt % S));
        if (XT > 1) {
            if ((kt + 1) % KT == 0) epilogue(kt / KT);
        }
    }
    if (XT == 1) epilogue(0);
}

// ---------------------------------------------------------------------------
// Pack megakernel: tiled weights/h + rope cos/sin table.
// ---------------------------------------------------------------------------
constexpr int PB_H    = 4096;
constexpr int PB_WQC  = 1024;
constexpr int PB_WQU  = 1024;
constexpr int PB_WK   = 256;
constexpr int PB_WV   = 256;
constexpr int PB_W1   = 4096;
constexpr int PB_W2   = 16384;
constexpr int PB_ROPE = 256;
constexpr int PB_TOTAL = PB_H + PB_WQC + PB_WQU + PB_WK + PB_WV + PB_W1 + PB_W2 + PB_ROPE;

__device__ __forceinline__ void pk_transpose(const float* __restrict__ src,
                                             __half* __restrict__ dst,
                                             int K, int N, int tile, int KTt, int nBase) {
    __shared__ float t[32][33];
    int tx = threadIdx.x & 31, ty = threadIdx.x >> 5;
    int ntx = N / 32;
    int n0 = (tile % ntx) * 32, k0 = (tile / ntx) * 32;
#pragma unroll
    for (int i = ty; i < 32; i += 8)
        t[i][tx] = src[(size_t)(k0 + i) * N + n0 + tx];
    __syncthreads();
#pragma unroll
    for (int i = ty; i < 32; i += 8) {
        int n = nBase + n0 + i;
        int k = k0 + tx;
        size_t tb = ((size_t)(n >> 7) * KTt + (k >> 6)) * TILE_H;
        uint32_t o = sw128((uint32_t)((n & 127) * 128 + (k & 63) * 2));
        *(__half*)((char*)dst + tb * 2 + o) = __float2half_rn(t[tx][i]);
    }
}

__global__ void __launch_bounds__(256)
pack_kernel(const float* __restrict__ h_in, __half* __restrict__ h_t,
            const float* __restrict__ wqc, __half* __restrict__ wqc_t,
            const float* __restrict__ wqu, __half* __restrict__ wqu_t,
            const float* __restrict__ wk,  const float* __restrict__ wv,
            __half* __restrict__ wkv_t,
            const float* __restrict__ w1,  __half* __restrict__ w1_t,
            const float* __restrict__ w2,  __half* __restrict__ w2_t,
            float* __restrict__ rope_tab) {
    int b = blockIdx.x;
    if (b < PB_H) {
        int m = b;
        size_t mtb = (size_t)(m >> 7) * 32;
        uint32_t rowo = (uint32_t)((m & 127) * 128);
        const float4* s4 = (const float4*)(h_in + (size_t)m * 2048);
        int k0 = threadIdx.x * 8;
        float4 va = s4[threadIdx.x * 2];
        float4 vb = s4[threadIdx.x * 2 + 1];
        __half2 h01 = __floats2half2_rn(va.x, va.y);
        __half2 h23 = __floats2half2_rn(va.z, va.w);
        __half2 h45 = __floats2half2_rn(vb.x, vb.y);
        __half2 h67 = __floats2half2_rn(vb.z, vb.w);
        uint4 pk;
        pk.x = *(uint32_t*)&h01; pk.y = *(uint32_t*)&h23;
        pk.z = *(uint32_t*)&h45; pk.w = *(uint32_t*)&h67;
        size_t tb = (mtb + (k0 >> 6)) * TILE_H;
        uint32_t o = sw128(rowo + (uint32_t)((k0 & 63) * 2));
        *(uint4*)((char*)h_t + tb * 2 + o) = pk;
        return;
    }
    b -= PB_H;
    if (b < PB_WQC) { pk_transpose(wqc, wqc_t, C_HID, C_QC, b, 32, 0); return; }
    b -= PB_WQC;
    if (b < PB_WQU) { pk_transpose(wqu, wqu_t, C_QC, C_H * C_D, b, 8, 0); return; }
    b -= PB_WQU;
    if (b < PB_WK)  { pk_transpose(wk, wkv_t, C_HID, C_D, b, 32, 0); return; }
    b -= PB_WK;
    if (b < PB_WV)  { pk_transpose(wv, wkv_t, C_HID, C_D, b, 32, 128); return; }
    b -= PB_WV;
    if (b < PB_W1) {
        int g = b / 1024, tile = b % 1024;
        pk_transpose(w1 + (size_t)g * 512 * 2048,
                     w1_t + (size_t)g * 128 * TILE_H,
                     512, 2048, tile, 8, 0);
        return;
    }
    b -= PB_W1;
    if (b < PB_W2) { pk_transpose(w2, w2_t, C_G * C_INTER, C_HID, b, 128, 0); return; }
    b -= PB_W2;
    {
        int idx  = b * 256 + threadIdx.x;
        int pos  = idx >> 5;
        int lane = idx & 31;
        double invd = exp(-log(10000.0) * (double)(2 * lane) / 64.0);
        double ang  = (double)pos * invd;
        rope_tab[pos * 64 + lane * 2]     = (float)cos(ang);
        rope_tab[pos * 64 + lane * 2 + 1] = (float)sin(ang);
    }
}

// ---------------------------------------------------------------------------
// RoPE + RMSNorm, emitting fp16 swizzled attention tiles directly.
// ---------------------------------------------------------------------------
__device__ __forceinline__ void st_att_half(__half* base, size_t tile, int row, int d, float v) {
    int idx = row * 128 + ((((d >> 3) ^ (row & 7)) << 3) | (d & 7));
    base[tile * 8192 + idx] = __float2half_rn(v);
}

__global__ void __launch_bounds__(256)
rope_kernel(const float* __restrict__ q, const float* __restrict__ kv,
            const float* __restrict__ qw, const float* __restrict__ kw,
            const float* __restrict__ rope_tab,
            __half* __restrict__ qs, __half* __restrict__ ks, __half* __restrict__ vs) {
    int gid  = blockIdx.x * blockDim.x + threadIdx.x;
    int wid  = gid >> 5;
    int lane = threadIdx.x & 31;

    const float scale = 0.08838834764831845f;
    bool isq = wid < C_TOK * C_H;
    const float* row;
    const float* w;
    int token, h = 0;
    if (isq) {
        token = wid >> 4; h = wid & 15;
        row = q + (size_t)wid * C_D;
        w = qw;
    } else {
        int wk2 = wid - C_TOK * C_H;
        if (wk2 >= C_TOK) return;
        token = wk2;
        row = kv + (size_t)token * (2 * C_D);
        w = kw;
    }
    int b = token >> 11;
    int t = token & (C_T - 1);

    float a  = row[lane];
    float b2 = row[lane + 32];
    float c  = row[lane + 64];
    float e  = row[lane + 96];

    float cs = rope_tab[t * 64 + lane * 2];
    float sn = rope_tab[t * 64 + lane * 2 + 1];

    float r1 = a * cs - b2 * sn;
    float r2 = a * sn + b2 * cs;

    float ss = r1 * r1 + r2 * r2 + c * c + e * e;
#pragma unroll
    for (int off = 16; off; off >>= 1) ss += __shfl_xor_sync(0xffffffffu, ss, off);
    float rms = rsqrtf(ss * (1.0f / 128.0f) + 1e-6f);

    float v0 = r1 * rms * w[lane];
    float v1 = r2 * rms * w[lane + 32];
    float v2 = c  * rms * w[lane + 64];
    float v3 = e  * rms * w[lane + 96];

    int rowi = t & 63;
    if (isq) {
        size_t tile = (size_t)((b * 16 + h) * 32 + (t >> 6));
        st_att_half(qs, tile, rowi, lane,      v0 * scale);
        st_att_half(qs, tile, rowi, lane + 32, v1 * scale);
        st_att_half(qs, tile, rowi, lane + 64, v2 * scale);
        st_att_half(qs, tile, rowi, lane + 96, v3 * scale);
    } else {
        size_t tile = (size_t)(b * 32 + (t >> 6));
        st_att_half(ks, tile, rowi, lane,      v0);
        st_att_half(ks, tile, rowi, lane + 32, v1);
        st_att_half(ks, tile, rowi, lane + 64, v2);
        st_att_half(ks, tile, rowi, lane + 96, v3);
        st_att_half(vs, tile, rowi, lane,      row[128 + lane]);
        st_att_half(vs, tile, rowi, lane + 32, row[160 + lane]);
        st_att_half(vs, tile, rowi, lane + 64, row[192 + lane]);
        st_att_half(vs, tile, rowi, lane + 96, row[224 + lane]);
    }
}

// ---------------------------------------------------------------------------
// fp16 MMA flash attention (unchanged).
// ---------------------------------------------------------------------------
__global__ void __launch_bounds__(128)
attn_kernel(const __half* __restrict__ qs, const __half* __restrict__ ks,
            const __half* __restrict__ vs, const float* __restrict__ sink,
            __half* __restrict__ att_t) {
    constexpr int TB = 16384;
    extern __shared__ __align__(16) char smc[];
    const uint32_t sbase = (uint32_t)__cvta_generic_to_shared(smc);
    const uint32_t mbq  = sbase;
    const uint32_t mbk0 = sbase + 16;
    const uint32_t Qb   = sbase + 1024;
    const uint32_t St   = Qb + TB;

    int qt = blockIdx.x, h = blockIdx.y, b = blockIdx.z;
    int tid = threadIdx.x, warp = tid >> 5, lane = tid & 31;
    int grp = lane >> 2, tig = lane & 3;
    int wr = warp * 16;

    if (tid == 0) { mbar_init(mbq, 1); mbar_init(mbk0, 1); mbar_init(mbk0 + 8, 1); }
    __syncthreads();

    int ktLo = qt > 8 ? qt - 8 : 0;
    int nT = qt - ktLo + 1;

    if (tid == 0) {
        mbar_expect(mbq, TB);
        bulk_g2s(Qb, qs + (size_t)((b * 16 + h) * 32 + qt) * 8192, TB, mbq);
        for (int i = 0; i < 2 && i < nT; i++) {
            uint32_t mb = mbk0 + 8 * i;
            mbar_expect(mb, 2 * TB);
            bulk_g2s(St + i * 2 * TB,      ks + (size_t)(b * 32 + ktLo + i) * 8192, TB, mb);
            bulk_g2s(St + i * 2 * TB + TB, vs + (size_t)(b * 32 + ktLo + i) * 8192, TB, mb);
        }
    }

    float o[16][4];
#pragma unroll
    for (int i = 0; i < 16; i++)
#pragma unroll
        for (int r = 0; r < 4; r++) o[i][r] = 0.f;
    float mA = -1e30f, mB = -1e30f, lA = 0.f, lB = 0.f;

    mbar_wait(mbq, 0);

    const uint32_t axr  = (uint32_t)(lane & 7);
    const uint32_t aBase = Qb + (uint32_t)(wr + (lane & 15)) * 256;
    const uint32_t aSel = (uint32_t)(lane >> 4);
    const int bsrow_off = ((lane >> 4) & 1) * 8 + (lane & 7);
    const uint32_t bsel = (uint32_t)((lane >> 3) & 1);
    const int vrow_off  = ((lane >> 3) & 1) * 8 + (lane & 7);
    const uint32_t vsel = (uint32_t)((lane >> 4) & 1);

    for (int i = 0; i < nT; i++) {
        int kt = ktLo + i;
        mbar_wait(mbk0 + 8 * (i & 1), (uint32_t)((i >> 1) & 1));
        const uint32_t Kb = St + (uint32_t)((i & 1) * 2 * TB);
        const uint32_t Vb = Kb + TB;

        float sc[8][4];
#pragma unroll
        for (int ni = 0; ni < 8; ni++)
#pragma unroll
            for (int r = 0; r < 4; r++) sc[ni][r] = 0.f;

#pragma unroll
        for (int k8 = 0; k8 < 8; k8++) {
            uint32_t a0, a1, a2, a3;
            ldsm4(a0, a1, a2, a3, aBase + (((uint32_t)(2 * k8) + aSel) ^ axr) * 16);
#pragma unroll
            for (int np = 0; np < 4; np++) {
                uint32_t b0, b1, b2, b3;
                uint32_t srow = (uint32_t)(np * 16 + bsrow_off);
                ldsm4(b0, b1, b2, b3,
                      Kb + srow * 256 + (((uint32_t)(2 * k8) + bsel) ^ axr) * 16);
                mma_f16(sc[np*2][0], sc[np*2][1], sc[np*2][2], sc[np*2][3],
                        a0, a1, a2, a3, b0, b1);
                mma_f16(sc[np*2+1][0], sc[np*2+1][1], sc[np*2+1][2], sc[np*2+1][3],
                        a0, a1, a2, a3, b2, b3);
            }
        }

        if (kt == qt || kt + 8 == qt) {
            int tA2 = qt * 64 + wr + grp;
            int s00 = kt * 64 + tig * 2;
#pragma unroll
            for (int ni = 0; ni < 8; ni++) {
#pragma unroll
                for (int r = 0; r < 4; r++) {
                    int s = s00 + ni * 8 + (r & 1);
                    int t = tA2 + (r >> 1) * 8;
                    if (s > t || s < t - (C_WIN - 1)) sc[ni][r] = -1e30f;
                }
            }
        }

        float mxA = -1e30f, mxB = -1e30f;
#pragma unroll
        for (int ni = 0; ni < 8; ni++) {
            mxA = fmaxf(mxA, fmaxf(sc[ni][0], sc[ni][1]));
            mxB = fmaxf(mxB, fmaxf(sc[ni][2], sc[ni][3]));
        }
        mxA = fmaxf(mxA, __shfl_xor_sync(0xffffffffu, mxA, 1));
        mxA = fmaxf(mxA, __shfl_xor_sync(0xffffffffu, mxA, 2));
        mxB = fmaxf(mxB, __shfl_xor_sync(0xffffffffu, mxB, 1));
        mxB = fmaxf(mxB, __shfl_xor_sync(0xffffffffu, mxB, 2));
        float nmA = fmaxf(mA, mxA), nmB = fmaxf(mB, mxB);
        float cA = __expf(mA - nmA), cB = __expf(mB - nmB);
        mA = nmA; mB = nmB;
        float sA = 0.f, sB = 0.f;
#pragma unroll
        for (int ni = 0; ni < 8; ni++) {
            sc[ni][0] = __expf(sc[ni][0] - nmA);
            sc[ni][1] = __expf(sc[ni][1] - nmA);
            sc[ni][2] = __expf(sc[ni][2] - nmB);
            sc[ni][3] = __expf(sc[ni][3] - nmB);
            sA += sc[ni][0] + sc[ni][1];
            sB += sc[ni][2] + sc[ni][3];
        }
        sA += __shfl_xor_sync(0xffffffffu, sA, 1);
        sA += __shfl_xor_sync(0xffffffffu, sA, 2);
        sB += __shfl_xor_sync(0xffffffffu, sB, 1);
        sB += __shfl_xor_sync(0xffffffffu, sB, 2);
        lA = lA * cA + sA;
        lB = lB * cB + sB;
#pragma unroll
        for (int nd = 0; nd < 16; nd++) {
            o[nd][0] *= cA; o[nd][1] *= cA;
            o[nd][2] *= cB; o[nd][3] *= cB;
        }

#pragma unroll
        for (int kp = 0; kp < 4; kp++) {
            __half2 p0 = __floats2half2_rn(sc[2*kp][0],   sc[2*kp][1]);
            __half2 p1 = __floats2half2_rn(sc[2*kp][2],   sc[2*kp][3]);
            __half2 p2 = __floats2half2_rn(sc[2*kp+1][0], sc[2*kp+1][1]);
            __half2 p3 = __floats2half2_rn(sc[2*kp+1][2], sc[2*kp+1][3]);
            uint32_t pa0 = *(uint32_t*)&p0, pa1 = *(uint32_t*)&p1;
            uint32_t pa2 = *(uint32_t*)&p2, pa3 = *(uint32_t*)&p3;
            uint32_t vrow = (uint32_t)(kp * 16 + vrow_off);
#pragma unroll
            for (int dp = 0; dp < 8; dp++) {
                uint32_t b0, b1, b2, b3;
                ldsm4t(b0, b1, b2, b3,
                       Vb + vrow * 256 + (((uint32_t)(2 * dp) + vsel) ^ axr) * 16);
                mma_f16(o[dp*2][0], o[dp*2][1], o[dp*2][2], o[dp*2][3],
                        pa0, pa1, pa2, pa3, b0, b1);
                mma_f16(o[dp*2+1][0], o[dp*2+1][1], o[dp*2+1][2], o[dp*2+1][3],
                        pa0, pa1, pa2, pa3, b2, b3);
            }
        }

        __syncthreads();
        if (tid == 0 && i + 2 < nT) {
            uint32_t mb = mbk0 + 8 * (i & 1);
            mbar_expect(mb, 2 * TB);
            bulk_g2s(St + (i & 1) * 2 * TB,      ks + (size_t)(b * 32 + kt + 2) * 8192, TB, mb);
            bulk_g2s(St + (i & 1) * 2 * TB + TB, vs + (size_t)(b * 32 + kt + 2) * 8192, TB, mb);
        }
    }

    float sl = sink[h];
    float nmA = fmaxf(mA, sl);
    float fA  = __expf(mA - nmA);
    float dA  = lA * fA + __expf(sl - nmA);
    float scAf = fA / dA;
    float nmB = fmaxf(mB, sl);
    float fB  = __expf(mB - nmB);
    float dB  = lB * fB + __expf(sl - nmB);
    float scBf = fB / dB;

    int tokenA = b * C_T + qt * 64 + wr + grp;
    int tokenB = tokenA + 8;
#pragma unroll
    for (int nd = 0; nd < 16; nd++) {
        int col = h * 128 + nd * 8 + tig * 2;
        {
            size_t tb = ((size_t)(tokenA >> 7) * 32 + (col >> 6)) * TILE_H;
            uint32_t off = sw128((uint32_t)((tokenA & 127) * 128 + (col & 63) * 2));
            __half2 hv = __floats2half2_rn(o[nd][0] * scAf, o[nd][1] * scAf);
            *(__half2*)((char*)att_t + tb * 2 + off) = hv;
        }
        {
            size_t tb = ((size_t)(tokenB >> 7) * 32 + (col >> 6)) * TILE_H;
            uint32_t off = sw128((uint32_t)((tokenB & 127) * 128 + (col & 63) * 2));
            __half2 hv = __floats2half2_rn(o[nd][2] * scBf, o[nd][3] * scBf);
            *(__half2*)((char*)att_t + tb * 2 + off) = hv;
        }
    }
}

// ---------------------------------------------------------------------------
extern "C" void kernel_launch(void* const* d_in, const int* in_sizes, int n_in,
                              void* d_out, int out_size) {
    const float* h_in     = (const float*)d_in[0];
    const float* wq_comp  = (const float*)d_in[1];
    const float* wq_up    = (const float*)d_in[2];
    const float* wk       = (const float*)d_in[3];
    const float* wv       = (const float*)d_in[4];
    const float* q_norm_w = (const float*)d_in[5];
    const float* k_norm_w = (const float*)d_in[6];
    const float* sink     = (const float*)d_in[7];
    const float* out_w1   = (const float*)d_in[8];
    const float* out_w2   = (const float*)d_in[9];
    float* out = (float*)d_out;

    __half *h_t, *hc_t, *att_t, *y1_t, *wqc_t, *wqu_t, *wkv_t, *w1_t, *w2_t, *qsp, *ksp, *vsp;
    float *q, *kv, *rope_tab;
    cudaGetSymbolAddress((void**)&h_t,   g_h_t);
    cudaGetSymbolAddress((void**)&hc_t,  g_hc_t);
    cudaGetSymbolAddress((void**)&att_t, g_att_t);
    cudaGetSymbolAddress((void**)&y1_t,  g_y1_t);
    cudaGetSymbolAddress((void**)&wqc_t, g_wqc_t);
    cudaGetSymbolAddress((void**)&wqu_t, g_wqu_t);
    cudaGetSymbolAddress((void**)&wkv_t, g_wkv_t);
    cudaGetSymbolAddress((void**)&w1_t,  g_w1_t);
    cudaGetSymbolAddress((void**)&w2_t,  g_w2_t);
    cudaGetSymbolAddress((void**)&q,     g_q);
    cudaGetSymbolAddress((void**)&kv,    g_kv);
    cudaGetSymbolAddress((void**)&rope_tab, g_rope);
    cudaGetSymbolAddress((void**)&qsp,   g_qs);
    cudaGetSymbolAddress((void**)&ksp,   g_ks);
    cudaGetSymbolAddress((void**)&vsp,   g_vs);

    constexpr int SM_TMA  = 1024 + 3 * 32768;            // 99328 B (2 CTAs/SM)
    constexpr int SM_ATTN = 1024 + 16384 + 2 * 32768;    // 82944 B
    cudaFuncSetAttribute((const void*)gemm_tma<0,1>, cudaFuncAttributeMaxDynamicSharedMemorySize, SM_TMA);
    cudaFuncSetAttribute((const void*)gemm_tma<0,2>, cudaFuncAttributeMaxDynamicSharedMemorySize, SM_TMA);
    cudaFuncSetAttribute((const void*)gemm_tma<1,2>, cudaFuncAttributeMaxDynamicSharedMemorySize, SM_TMA);
    cudaFuncSetAttribute((const void*)gemm_tma<3,1>, cudaFuncAttributeMaxDynamicSharedMemorySize, SM_TMA);
    cudaFuncSetAttribute((const void*)attn_kernel, cudaFuncAttributeMaxDynamicSharedMemorySize, SM_ATTN);

    // [0] pack (+ rope table)
    pack_kernel<<<PB_TOTAL, 256>>>(h_in, h_t, wq_comp, wqc_t, wq_up, wqu_t,
                                   wk, wv, wkv_t, out_w1, w1_t, out_w2, w2_t, rope_tab);

    // [1] merged: hc = h @ wq_comp (x<4, half tiled) | kv = h @ wkv (x>=4, fp32)
    gemm_tma<3,1><<<dim3(6, 32), 256, SM_TMA>>>(
        h_t, wqc_t, wkv_t, kv, hc_t, 32, 32, 32, 0, 0, 0, 0);

    // [2] q = hc @ wq_up    -> fp32 (KT=8, XT=2)
    gemm_tma<0,2><<<dim3(8, 32), 256, SM_TMA>>>(
        hc_t, wqu_t, nullptr, q, nullptr, 8, 8, 8, 0, 0, C_H * C_D, 0);

    // [3] RoPE + RMSNorm -> fp16 swizzled q/k/v tiles
    {
        int warps = C_TOK * C_H + C_TOK;
        rope_kernel<<<(warps * 32 + 255) / 256, 256>>>(q, kv, q_norm_w, k_norm_w,
                                                       rope_tab, qsp, ksp, vsp);
    }

    // [4] flash attention -> att half tiled
    attn_kernel<<<dim3(32, 16, 2), 128, SM_ATTN>>>(qsp, ksp, vsp, sink, att_t);

    // [5] y1 = grouped att @ w1 -> half tiled (KT=8, XT=2)
    gemm_tma<1,2><<<dim3(8, 32, C_G), 256, SM_TMA>>>(
        att_t, w1_t, nullptr, nullptr, y1_t, 8, 32, 8, 8, 128, 128, 32);

    // [6] out = y1 @ out_w2 -> fp32 (KT=128)
    gemm_tma<0,1><<<dim3(16, 32), 256, SM_TMA>>>(
        y1_t, w2_t, nullptr, out, nullptr, 128, 128, 128, 0, 0, C_HID, 0);
}